// round 16
// baseline (speedup 1.0000x reference)
#include <cuda_runtime.h>
#include <cuda_bf16.h>
#include <math.h>

// ---------------------------------------------------------------------------
// SecDecoder outputs (flattened, concatenated in tuple order)
//   rp        [total]     = (M @ arange(ncol)) / ncol
//   gaps_start[nseq]      = sa[start_row]/ncol
//   gaps_in   [n_keep]    = (sa[g+1]-sa[g]-1)/ncol, g not a seq boundary
//   gaps_end  [nseq]      = (ncol - sa[end_row] - 1)/ncol
//   col_dist  [ncol*nout] = softmax(columns @ W + b)
//
// R8/R15 structure (empirical optimum):
//   ad_kernel : block 0 = cumsum+uniformity, blocks [1,129) = col_dist
//               (hidden under the stream), rest = soft_argmax at ~87% HBM.
//   bc_kernel : gaps. R16 micro-opt: prefetch the two g_sa operands before
//               the mode flag (overlapped latencies) and smem-broadcast
//               g_uniL (391 L2 requests instead of 3128 same-address ones).
// ---------------------------------------------------------------------------

#define MAX_TOTAL 131072
#define MAX_NSEQ  1024
#define NOUT      26     // fixed by problem
#define KMAX      16     // dcol/32 (dcol = 512)
#define DBLOCKS   128    // coldist blocks (ncol/8)
#define ABASE     (1 + DBLOCKS)   // first A block index

__device__ float g_sa[MAX_TOTAL];  // soft_argmax scratch
__device__ int   g_cs[MAX_NSEQ];   // cumsum(sequence_lengths), fits int32
__device__ int   g_uniL;           // uniform length if all equal, else 0

// Dtype-agnostic sequence_lengths accessor (harness may pass int64 or int32).
// Lengths are strictly positive; little-endian int64 => word[1]==0.
__device__ __forceinline__ bool sl_is_int64(const void* sl) {
    return ((const int*)sl)[1] == 0;
}
__device__ __forceinline__ int sl_get(const void* sl, bool is64, int i) {
    if (is64) return (int)((const long long*)sl)[i];
    return ((const int*)sl)[i];
}

// ---------------------------------------------------------------------------
__global__ void __launch_bounds__(256) ad_kernel(
    const float* __restrict__ M, float* __restrict__ out,
    const float* __restrict__ columns, const float* __restrict__ W,
    const float* __restrict__ b, const void* __restrict__ sl,
    int total, int ncol, int dcol, int nseq, float inv_ncol, int off_cd)
{
    int tid  = threadIdx.x;
    int warp = tid >> 5;
    int lane = tid & 31;

    if (blockIdx.x >= ABASE) {
        // ---------------- A: soft_argmax, one warp per row ----------------
        int row_i = (blockIdx.x - ABASE) * 8 + warp;
        if (row_i >= total) return;

        const float4* row = reinterpret_cast<const float4*>(M)
                          + (size_t)row_i * (ncol >> 2);
        float sum = 0.f;
        int nvec = ncol >> 2;
#pragma unroll 8
        for (int k = lane; k < nvec; k += 32) {
            float4 v = __ldcs(row + k);        // read-once: evict-first
            float c = (float)(k << 2);
            sum = fmaf(v.x, c,        sum);
            sum = fmaf(v.y, c + 1.0f, sum);
            sum = fmaf(v.z, c + 2.0f, sum);
            sum = fmaf(v.w, c + 3.0f, sum);
        }
#pragma unroll
        for (int o = 16; o; o >>= 1)
            sum += __shfl_down_sync(0xffffffffu, sum, o);

        if (lane == 0) {
            g_sa[row_i] = sum;
            out[row_i]  = sum * inv_ncol;
        }
        return;
    }

    if (blockIdx.x == 0) {
        // ------- cumsum via warp shuffle-scan + uniformity detection -------
        if (warp == 0) {
            bool is64 = sl_is_int64(sl);
            int L0 = sl_get(sl, is64, 0);
            int carry = 0;
            bool uni = true;
            int nchunks = (nseq + 31) >> 5;
            for (int c = 0; c < nchunks; c++) {
                int i = (c << 5) + lane;
                int v = (i < nseq) ? sl_get(sl, is64, i) : 0;
                if (i < nseq && v != L0) uni = false;
#pragma unroll
                for (int s = 1; s < 32; s <<= 1) {
                    int u = __shfl_up_sync(0xffffffffu, v, s);
                    if (lane >= s) v += u;
                }
                v += carry;
                if (i < nseq) g_cs[i] = v;
                carry = __shfl_sync(0xffffffffu, v, 31);
            }
            bool all_uni = __all_sync(0xffffffffu, uni);
            if (lane == 0) g_uniL = all_uni ? L0 : 0;
        }
        return;
    }

    // ---------------- D: col_dist, one warp per column-row ----------------
    int r = (blockIdx.x - 1) * 8 + warp;   // < 1024 always

    // prefetch x: 16 independent LDGs up front (one DRAM latency)
    float x[KMAX];
    {
        const float* crow = columns + (size_t)r * dcol;
#pragma unroll
        for (int k = 0; k < KMAX; k++)
            x[k] = __ldg(crow + (k << 5) + lane);
    }

    float acc[NOUT];
#pragma unroll
    for (int o = 0; o < NOUT; o++) acc[o] = 0.f;

    // W read through L1/L2 (53 KB, resident after warm-up; hidden under A)
#pragma unroll
    for (int k = 0; k < KMAX; k++) {
        const float* wrow = W + (size_t)((k << 5) + lane) * NOUT;
        float xv = x[k];
#pragma unroll
        for (int o = 0; o < NOUT; o++)
            acc[o] = fmaf(xv, __ldg(wrow + o), acc[o]);
    }

    // butterfly-reduce each accumulator across the warp
#pragma unroll
    for (int o = 0; o < NOUT; o++) {
#pragma unroll
        for (int sft = 16; sft; sft >>= 1)
            acc[o] += __shfl_xor_sync(0xffffffffu, acc[o], sft);
    }

    // lane o takes logit o (+ bias); softmax across lanes
    float val = -INFINITY;
#pragma unroll
    for (int o = 0; o < NOUT; o++)
        if (lane == o) val = acc[o];
    bool active = (lane < NOUT);
    if (active) val += __ldg(b + lane);
    else        val  = -INFINITY;

    float m = val;
#pragma unroll
    for (int sft = 16; sft; sft >>= 1)
        m = fmaxf(m, __shfl_xor_sync(0xffffffffu, m, sft));
    float e = active ? expf(val - m) : 0.f;
    float sum = e;
#pragma unroll
    for (int sft = 16; sft; sft >>= 1)
        sum += __shfl_xor_sync(0xffffffffu, sum, sft);

    if (active) out[off_cd + (size_t)r * NOUT + lane] = e / sum;
}

// ---------------------------------------------------------------------------
// Kernel BC: boundary + interior gaps.
// R16: issue the two g_sa loads FIRST (addresses independent of the mode
// flag -> latencies overlap), and broadcast g_uniL via smem (one L2 request
// per block instead of one per warp, all to the same sector).
// ---------------------------------------------------------------------------
__global__ void __launch_bounds__(256) bc_kernel(
    float* __restrict__ out,
    int nseq, int total, float ncolf, float inv_ncol,
    int off_gs, int off_gin, int off_ge)
{
    __shared__ int Ls;
    int gt = blockIdx.x * 256 + threadIdx.x;

    // prefetch interior-gap operands immediately (independent of mode)
    bool hasgap = (gt < total - 1);
    float sa0 = 0.f, sa1 = 0.f;
    if (hasgap) {
        sa0 = __ldg(&g_sa[gt]);
        sa1 = __ldg(&g_sa[gt + 1]);
    }

    if (threadIdx.x == 0) Ls = __ldcg(&g_uniL);
    __syncthreads();
    int L = Ls;

    if (L > 0) {
        // ------------------------- uniform fast path -------------------------
        if (gt < nseq) {
            int row0 = gt * L;
            int rowe = row0 + L - 1;
            out[off_gs + gt] = __ldg(&g_sa[row0]) * inv_ncol;
            out[off_ge + gt] = (ncolf - __ldg(&g_sa[rowe]) - 1.0f) * inv_ncol;
        }
        if (!hasgap) return;

        int cnt = gt / L;
        if (cnt > nseq - 1) cnt = nseq - 1;
        bool removed = (cnt < nseq - 1) && ((cnt + 1) * L == gt + 1);
        if (!removed)
            out[off_gin + (gt - cnt)] = (sa1 - sa0 - 1.0f) * inv_ncol;
        return;
    }

    // --------------------- general path (non-uniform) ---------------------
    if (gt < nseq) {
        int cs_t = __ldg(&g_cs[gt]);
        int row0 = (gt == 0) ? 0 : __ldg(&g_cs[gt - 1]);
        out[off_gs + gt] = __ldg(&g_sa[row0]) * inv_ncol;
        out[off_ge + gt] = (ncolf - __ldg(&g_sa[cs_t - 1]) - 1.0f) * inv_ncol;
    }
    if (!hasgap) return;

    int lo = 0, hi = nseq - 1;
    while (lo < hi) {
        int mid = (lo + hi) >> 1;
        if (__ldg(&g_cs[mid]) <= gt) lo = mid + 1; else hi = mid;
    }
    int cnt = lo;
    bool removed = (cnt < nseq - 1) && (__ldg(&g_cs[cnt]) == gt + 1);
    if (!removed)
        out[off_gin + (gt - cnt)] = (sa1 - sa0 - 1.0f) * inv_ncol;
}

// ---------------------------------------------------------------------------
extern "C" void kernel_launch(void* const* d_in, const int* in_sizes, int n_in,
                              void* d_out, int out_size)
{
    const float* M    = (const float*)d_in[0];
    const float* cols = (const float*)d_in[1];
    const void*  sl   = d_in[2];            // int32 or int64, probed on device
    const float* W    = (const float*)d_in[3];
    const float* b    = (const float*)d_in[4];
    float*       out  = (float*)d_out;

    int nout  = in_sizes[4];                // 26
    int dcol  = in_sizes[3] / nout;         // 512
    int ncol  = in_sizes[1] / dcol;         // 1024
    int total = in_sizes[0] / ncol;         // 100000
    int nseq  = in_sizes[2];                // 500

    float ncolf    = (float)ncol;
    float inv_ncol = 1.0f / ncolf;

    int n_keep  = (total - 1) - (nseq - 1);
    int off_gs  = total;
    int off_gin = total + nseq;
    int off_ge  = off_gin + n_keep;
    int off_cd  = off_ge + nseq;

    // AD: fused cumsum/uniformity + col_dist + soft_argmax stream
    {
        int a_blocks = (total + 7) / 8;     // 12500
        ad_kernel<<<ABASE + a_blocks, 256>>>(
            M, out, cols, W, b, sl, total, ncol, dcol, nseq, inv_ncol, off_cd);
    }
    // BC: boundary + interior gaps
    {
        int blocks = (total - 1 + 255) / 256;
        bc_kernel<<<blocks, 256>>>(out, nseq, total, ncolf, inv_ncol,
                                   off_gs, off_gin, off_ge);
    }
}